// round 8
// baseline (speedup 1.0000x reference)
#include <cuda_runtime.h>
#include <cstdint>
#include <cstddef>

#define MAX_N 100000
#define MAX_E 1600000

// Scratch (no cudaMalloc allowed).
__device__ float g_pre[(size_t)MAX_N * 128];   // x@W1a + b1 per node
__device__ float g_M[(size_t)MAX_N * 128];     // mean of relu(...) per node
__device__ int   g_cnt[MAX_N];                 // in-degree
__device__ int   g_off[MAX_N];                 // bucket start
__device__ int   g_cur[MAX_N];                 // bucket write cursor
__device__ int2  g_pairs[MAX_E];               // {edge id, src node} grouped by dst
__device__ int   g_cursor;                     // global bucket allocator
__device__ int   g_is64;                       // edge_index dtype flag

// ---------------------------------------------------------------------------
// Detect edge_index element width (int64 indices < 2^17 -> odd words all 0).
// ---------------------------------------------------------------------------
__global__ void detect_kernel(const int* __restrict__ ei32, int n_words) {
    __shared__ int nonzero;
    if (threadIdx.x == 0) nonzero = 0;
    __syncthreads();
    const int idx = 1 + 2 * threadIdx.x;
    if (idx < n_words && ei32[idx] != 0) atomicOr(&nonzero, 1);
    __syncthreads();
    if (threadIdx.x == 0) g_is64 = (nonzero == 0) ? 1 : 0;
}

__device__ __forceinline__ int load_idx(const void* ei_raw, int is64, size_t pos) {
    return is64 ? (int)((const long long*)ei_raw)[pos]
                : ((const int*)ei_raw)[pos];
}

// ---------------------------------------------------------------------------
// Bucket sort by destination: histogram -> offsets -> permutation.
// ---------------------------------------------------------------------------
__global__ __launch_bounds__(256) void hist_kernel(const void* __restrict__ ei_raw,
                                                   int nE, int nN) {
    const int e = blockIdx.x * blockDim.x + threadIdx.x;
    const int is64 = g_is64;
    if (e < nE) {
        const int dst = load_idx(ei_raw, is64, e);
        if ((unsigned)dst < (unsigned)nN) atomicAdd(&g_cnt[dst], 1);
    }
}

__global__ __launch_bounds__(256) void offset_kernel(int nN) {
    const int v = blockIdx.x * blockDim.x + threadIdx.x;
    const int lane = threadIdx.x & 31;
    const int c = (v < nN) ? g_cnt[v] : 0;
    int s = c;  // inclusive warp scan
#pragma unroll
    for (int d = 1; d < 32; d <<= 1) {
        const int t = __shfl_up_sync(0xffffffffu, s, d);
        if (lane >= d) s += t;
    }
    const int total = __shfl_sync(0xffffffffu, s, 31);
    int base = 0;
    if (lane == 31) base = atomicAdd(&g_cursor, total);
    base = __shfl_sync(0xffffffffu, base, 31);
    const int off = base + s - c;  // exclusive within warp
    if (v < nN) { g_off[v] = off; g_cur[v] = off; }
}

__global__ __launch_bounds__(256) void scatter_kernel(const void* __restrict__ ei_raw,
                                                      int nE, int nN) {
    const int e = blockIdx.x * blockDim.x + threadIdx.x;
    const int is64 = g_is64;
    if (e < nE) {
        const int dst = load_idx(ei_raw, is64, e);
        const int src = load_idx(ei_raw, is64, (size_t)nE + e);
        if ((unsigned)dst < (unsigned)nN && (unsigned)src < (unsigned)nN) {
            const int pos = atomicAdd(&g_cur[dst], 1);
            g_pairs[pos] = make_int2(e, src);
        }
    }
}

// ---------------------------------------------------------------------------
// pre = x @ W1[0:128,:] + b1        (N x 128, K=128)
// ---------------------------------------------------------------------------
__global__ __launch_bounds__(256) void pre_kernel(const float* __restrict__ x,
                                                  const float* __restrict__ W1,
                                                  const float* __restrict__ b1,
                                                  int n) {
    __shared__ float As[64][33];
    __shared__ float Ws[32][128];
    const int tid = threadIdx.x;
    const int n0 = blockIdx.x * 64;
    const int rg = tid & 15;
    const int cg = tid >> 4;

    float acc[4][8];
#pragma unroll
    for (int i = 0; i < 4; i++)
#pragma unroll
        for (int j = 0; j < 8; j++) acc[i][j] = 0.f;

    for (int k0 = 0; k0 < 128; k0 += 32) {
        {
            const int r = tid >> 3;
            const int kq = (tid & 7) * 4;
#pragma unroll
            for (int rr = 0; rr < 64; rr += 32) {
                const int row = r + rr;
                const int node = n0 + row;
                float4 v = make_float4(0.f, 0.f, 0.f, 0.f);
                if (node < n) v = *(const float4*)&x[(size_t)node * 128 + k0 + kq];
                As[row][kq] = v.x; As[row][kq + 1] = v.y;
                As[row][kq + 2] = v.z; As[row][kq + 3] = v.w;
            }
        }
        {
            const int k = tid >> 5;
            const int c = (tid & 31) * 4;
#pragma unroll
            for (int kk = 0; kk < 32; kk += 8)
                *(float4*)&Ws[k + kk][c] =
                    *(const float4*)&W1[(size_t)(k0 + k + kk) * 128 + c];
        }
        __syncthreads();
#pragma unroll
        for (int k2 = 0; k2 < 32; k2++) {
            const float4 w0 = *(const float4*)&Ws[k2][cg * 8];
            const float4 w1 = *(const float4*)&Ws[k2][cg * 8 + 4];
#pragma unroll
            for (int i = 0; i < 4; i++) {
                const float a = As[rg * 4 + i][k2];
                acc[i][0] += a * w0.x; acc[i][1] += a * w0.y;
                acc[i][2] += a * w0.z; acc[i][3] += a * w0.w;
                acc[i][4] += a * w1.x; acc[i][5] += a * w1.y;
                acc[i][6] += a * w1.z; acc[i][7] += a * w1.w;
            }
        }
        __syncthreads();
    }

    const float4 bb0 = *(const float4*)&b1[cg * 8];
    const float4 bb1 = *(const float4*)&b1[cg * 8 + 4];
#pragma unroll
    for (int i = 0; i < 4; i++) {
        const int node = n0 + rg * 4 + i;
        if (node < n) {
            float4 o0 = make_float4(acc[i][0] + bb0.x, acc[i][1] + bb0.y,
                                    acc[i][2] + bb0.z, acc[i][3] + bb0.w);
            float4 o1 = make_float4(acc[i][4] + bb1.x, acc[i][5] + bb1.y,
                                    acc[i][6] + bb1.z, acc[i][7] + bb1.w);
            *(float4*)&g_pre[(size_t)node * 128 + cg * 8] = o0;
            *(float4*)&g_pre[(size_t)node * 128 + cg * 8 + 4] = o1;
        }
    }
}

// ---------------------------------------------------------------------------
// Aggregate v2: one warp per node, chunk-of-4 software pipeline.
//   M[v] = mean_e relu(pre[src_e] + ea[e] @ W1[128:144,:])
// Chunk load: 4 pairs coalesced (lanes 0-3), broadcast by shfl, then 4 pre
// gathers + 4 ea loads issued back-to-back (MLP ~8/lane). Two-stage pipeline:
// chunk i+1 loads in flight while chunk i computes.
// ---------------------------------------------------------------------------
struct Chunk {
    float4 pr[4];
    float  eav[4];
    int    m;
};

__device__ __forceinline__ void load_chunk(Chunk& c, int i, int end, int lane,
                                           const float4* __restrict__ pre4,
                                           const float* __restrict__ ea) {
    c.m = end - i;
    if (c.m > 4) c.m = 4;
    int2 p = make_int2(0, 0);
    if (lane < c.m) p = g_pairs[i + lane];
#pragma unroll
    for (int j = 0; j < 4; j++) {
        const int ej = __shfl_sync(0xffffffffu, p.x, j);
        const int sj = __shfl_sync(0xffffffffu, p.y, j);
        if (j < c.m) {
            c.pr[j]  = pre4[(size_t)sj * 32 + lane];
            c.eav[j] = (lane < 16) ? ea[(size_t)ej * 16 + lane] : 0.f;
        }
    }
}

__device__ __forceinline__ void compute_chunk(const Chunk& c, float4& acc,
                                              const float4 (*W1b)[32], int lane) {
#pragma unroll
    for (int j = 0; j < 4; j++) {
        if (j >= c.m) break;
        float4 t = make_float4(0.f, 0.f, 0.f, 0.f);
#pragma unroll
        for (int k = 0; k < 16; k++) {
            const float a = __shfl_sync(0xffffffffu, c.eav[j], k);
            const float4 w = W1b[k][lane];
            t.x += a * w.x; t.y += a * w.y; t.z += a * w.z; t.w += a * w.w;
        }
        acc.x += fmaxf(c.pr[j].x + t.x, 0.f);
        acc.y += fmaxf(c.pr[j].y + t.y, 0.f);
        acc.z += fmaxf(c.pr[j].z + t.z, 0.f);
        acc.w += fmaxf(c.pr[j].w + t.w, 0.f);
    }
}

__global__ __launch_bounds__(256) void agg_kernel(const float* __restrict__ ea,
                                                  const float* __restrict__ W1,
                                                  int nN) {
    __shared__ float4 W1b[16][32];
    const int tid = threadIdx.x;
    for (int idx = tid; idx < 512; idx += 256) {
        const int k = idx >> 5, c = idx & 31;
        W1b[k][c] = *(const float4*)&W1[(size_t)(128 + k) * 128 + c * 4];
    }
    __syncthreads();

    const int lane = tid & 31;
    const int v = blockIdx.x * 8 + (tid >> 5);
    if (v >= nN) return;

    const int beg = g_off[v];
    const int cnt = g_cnt[v];
    const int end = beg + cnt;
    const float4* pre4 = (const float4*)g_pre;

    float4 acc = make_float4(0.f, 0.f, 0.f, 0.f);

    Chunk c0, c1;
    int i = beg;
    if (i < end) {
        load_chunk(c0, i, end, lane, pre4, ea);
        i += 4;
        while (i < end) {
            load_chunk(c1, i, end, lane, pre4, ea);   // prefetch next
            i += 4;
            compute_chunk(c0, acc, W1b, lane);        // compute current
            c0 = c1;
        }
        compute_chunk(c0, acc, W1b, lane);
    }

    const float inv = (cnt > 0) ? (1.f / (float)cnt) : 0.f;
    acc.x *= inv; acc.y *= inv; acc.z *= inv; acc.w *= inv;
    ((float4*)g_M)[(size_t)v * 32 + lane] = acc;
}

// ---------------------------------------------------------------------------
// Node kernel: fused 3-GEMM chain on 64-node tiles.
//   h1 = cnt>0 ? M @ W2 + b2 : 0
//   h2 = relu(h1 @ W3 + b3)
//   out = h2 @ W4 + b4
// ---------------------------------------------------------------------------
__device__ __forceinline__ void gemm128(const float* __restrict__ Ain,
                                        const float* __restrict__ Wg,
                                        float* __restrict__ Wc,
                                        float acc[4][8], int rg, int cg, int tid) {
#pragma unroll
    for (int i = 0; i < 4; i++)
#pragma unroll
        for (int j = 0; j < 8; j++) acc[i][j] = 0.f;

    for (int k0 = 0; k0 < 128; k0 += 32) {
        const int k = tid >> 5;
        const int c = (tid & 31) * 4;
#pragma unroll
        for (int kk = 0; kk < 32; kk += 8)
            *(float4*)&Wc[(k + kk) * 128 + c] =
                *(const float4*)&Wg[(size_t)(k0 + k + kk) * 128 + c];
        __syncthreads();
#pragma unroll
        for (int k2 = 0; k2 < 32; k2++) {
            const float4 w0 = *(const float4*)&Wc[k2 * 128 + cg * 8];
            const float4 w1 = *(const float4*)&Wc[k2 * 128 + cg * 8 + 4];
#pragma unroll
            for (int i = 0; i < 4; i++) {
                const float a = Ain[(rg * 4 + i) * 129 + k0 + k2];
                acc[i][0] += a * w0.x; acc[i][1] += a * w0.y;
                acc[i][2] += a * w0.z; acc[i][3] += a * w0.w;
                acc[i][4] += a * w1.x; acc[i][5] += a * w1.y;
                acc[i][6] += a * w1.z; acc[i][7] += a * w1.w;
            }
        }
        __syncthreads();
    }
}

__global__ __launch_bounds__(256) void node_kernel(const float* __restrict__ W2,
                                                   const float* __restrict__ b2,
                                                   const float* __restrict__ W3,
                                                   const float* __restrict__ b3,
                                                   const float* __restrict__ W4,
                                                   const float* __restrict__ b4,
                                                   float* __restrict__ out, int n) {
    extern __shared__ float sm[];
    float* A  = sm;                      // [64][129]
    float* B  = sm + 64 * 129;           // [64][129]
    float* Wc = sm + 2 * 64 * 129;       // [32][128]
    float* zf = Wc + 32 * 128;           // [64] cnt==0 flags

    const int tid = threadIdx.x;
    const int n0 = blockIdx.x * 64;
    const int rg = tid & 15;
    const int cg = tid >> 4;

    // Load mean operand (already divided) into A, flag empty nodes.
    {
        const int r = tid >> 2;
        const int q = (tid & 3) * 4;
        const int node = n0 + r;
        if ((tid & 3) == 0)
            zf[r] = (node < n && g_cnt[node] > 0) ? 0.f : 1.f;
#pragma unroll
        for (int k = q; k < 128; k += 16) {
            float4 v = make_float4(0.f, 0.f, 0.f, 0.f);
            if (node < n) v = *(const float4*)&g_M[(size_t)node * 128 + k];
            A[r * 129 + k]     = v.x;
            A[r * 129 + k + 1] = v.y;
            A[r * 129 + k + 2] = v.z;
            A[r * 129 + k + 3] = v.w;
        }
    }
    __syncthreads();

    float acc[4][8];

    // Stage 1: B = (cnt>0) ? A@W2 + b2 : 0
    gemm128(A, W2, Wc, acc, rg, cg, tid);
    {
        const float4 bb0 = *(const float4*)&b2[cg * 8];
        const float4 bb1 = *(const float4*)&b2[cg * 8 + 4];
        const float bb[8] = {bb0.x, bb0.y, bb0.z, bb0.w, bb1.x, bb1.y, bb1.z, bb1.w};
#pragma unroll
        for (int i = 0; i < 4; i++) {
            const int row = rg * 4 + i;
            const float zero = zf[row];
#pragma unroll
            for (int j = 0; j < 8; j++)
                B[row * 129 + cg * 8 + j] = (zero > 0.f) ? 0.f : (acc[i][j] + bb[j]);
        }
    }
    __syncthreads();

    // Stage 2: A = relu(B@W3 + b3)
    gemm128(B, W3, Wc, acc, rg, cg, tid);
    {
        const float4 bb0 = *(const float4*)&b3[cg * 8];
        const float4 bb1 = *(const float4*)&b3[cg * 8 + 4];
        const float bb[8] = {bb0.x, bb0.y, bb0.z, bb0.w, bb1.x, bb1.y, bb1.z, bb1.w};
#pragma unroll
        for (int i = 0; i < 4; i++) {
            const int row = rg * 4 + i;
#pragma unroll
            for (int j = 0; j < 8; j++)
                A[row * 129 + cg * 8 + j] = fmaxf(acc[i][j] + bb[j], 0.f);
        }
    }
    __syncthreads();

    // Stage 3: out = A@W4 + b4
    gemm128(A, W4, Wc, acc, rg, cg, tid);
    {
        const float4 bb0 = *(const float4*)&b4[cg * 8];
        const float4 bb1 = *(const float4*)&b4[cg * 8 + 4];
#pragma unroll
        for (int i = 0; i < 4; i++) {
            const int node = n0 + rg * 4 + i;
            if (node < n) {
                float4 o0 = make_float4(acc[i][0] + bb0.x, acc[i][1] + bb0.y,
                                        acc[i][2] + bb0.z, acc[i][3] + bb0.w);
                float4 o1 = make_float4(acc[i][4] + bb1.x, acc[i][5] + bb1.y,
                                        acc[i][6] + bb1.z, acc[i][7] + bb1.w);
                *(float4*)&out[(size_t)node * 128 + cg * 8] = o0;
                *(float4*)&out[(size_t)node * 128 + cg * 8 + 4] = o1;
            }
        }
    }
}

// ---------------------------------------------------------------------------
extern "C" void kernel_launch(void* const* d_in, const int* in_sizes, int n_in,
                              void* d_out, int out_size) {
    const float* x  = (const float*)d_in[0];
    const void*  ei = d_in[1];          // int32 or int64 — detected on device
    const float* ea = (const float*)d_in[2];
    // d_in[3] = batch (unused)
    const float* W1 = (const float*)d_in[4];
    const float* b1 = (const float*)d_in[5];
    const float* W2 = (const float*)d_in[6];
    const float* b2 = (const float*)d_in[7];
    const float* W3 = (const float*)d_in[8];
    const float* b3 = (const float*)d_in[9];
    const float* W4 = (const float*)d_in[10];
    const float* b4 = (const float*)d_in[11];
    float* out = (float*)d_out;

    const int n  = in_sizes[0] / 128;   // nodes
    const int nE = in_sizes[1] / 2;     // edges

    void* pC = nullptr; void* pX = nullptr;
    cudaGetSymbolAddress(&pC, g_cnt);
    cudaGetSymbolAddress(&pX, g_cursor);
    cudaMemsetAsync(pC, 0, (size_t)n * sizeof(int), 0);
    cudaMemsetAsync(pX, 0, sizeof(int), 0);

    const int ebl = (nE + 255) / 256;
    const int nbl = (n + 255) / 256;

    detect_kernel<<<1, 256>>>((const int*)ei, 2 * nE);
    hist_kernel<<<ebl, 256>>>(ei, nE, n);
    offset_kernel<<<nbl, 256>>>(n);
    scatter_kernel<<<ebl, 256>>>(ei, nE, n);

    const int nb64 = (n + 63) / 64;
    pre_kernel<<<nb64, 256>>>(x, W1, b1, n);
    agg_kernel<<<(n + 7) / 8, 256>>>(ea, W1, n);

    const size_t shmem = (size_t)(2 * 64 * 129 + 32 * 128 + 64) * sizeof(float);
    cudaFuncSetAttribute(node_kernel,
                         cudaFuncAttributeMaxDynamicSharedMemorySize, (int)shmem);
    node_kernel<<<nb64, 256, shmem>>>(W2, b2, W3, b3, W4, b4, out, n);
}

// round 9
// speedup vs baseline: 1.0032x; 1.0032x over previous
#include <cuda_runtime.h>
#include <cstdint>
#include <cstddef>

#define MAX_N 100000
#define MAX_E 1600000

// Scratch (no cudaMalloc allowed).
__device__ float g_pre[(size_t)MAX_N * 128];   // x@W1a + b1 per node
__device__ float g_M[(size_t)MAX_N * 128];     // mean of relu(...) per node
__device__ int   g_cnt[MAX_N];                 // in-degree
__device__ int   g_off[MAX_N];                 // bucket start
__device__ int   g_cur[MAX_N];                 // bucket write cursor
__device__ int2  g_pairs[MAX_E];               // {edge id, src node} grouped by dst
__device__ int   g_cursor;                     // global bucket allocator
__device__ int   g_is64;                       // edge_index dtype flag

// ---------------------------------------------------------------------------
// Detect edge_index element width (int64 indices < 2^17 -> odd words all 0).
// ---------------------------------------------------------------------------
__global__ void detect_kernel(const int* __restrict__ ei32, int n_words) {
    __shared__ int nonzero;
    if (threadIdx.x == 0) nonzero = 0;
    __syncthreads();
    const int idx = 1 + 2 * threadIdx.x;
    if (idx < n_words && ei32[idx] != 0) atomicOr(&nonzero, 1);
    __syncthreads();
    if (threadIdx.x == 0) g_is64 = (nonzero == 0) ? 1 : 0;
}

__device__ __forceinline__ int load_idx(const void* ei_raw, int is64, size_t pos) {
    return is64 ? (int)((const long long*)ei_raw)[pos]
                : ((const int*)ei_raw)[pos];
}

// ---------------------------------------------------------------------------
// Bucket sort by destination: histogram -> offsets -> permutation.
// ---------------------------------------------------------------------------
__global__ __launch_bounds__(256) void hist_kernel(const void* __restrict__ ei_raw,
                                                   int nE, int nN) {
    const int e = blockIdx.x * blockDim.x + threadIdx.x;
    const int is64 = g_is64;
    if (e < nE) {
        const int dst = load_idx(ei_raw, is64, e);
        if ((unsigned)dst < (unsigned)nN) atomicAdd(&g_cnt[dst], 1);
    }
}

__global__ __launch_bounds__(256) void offset_kernel(int nN) {
    const int v = blockIdx.x * blockDim.x + threadIdx.x;
    const int lane = threadIdx.x & 31;
    const int c = (v < nN) ? g_cnt[v] : 0;
    int s = c;  // inclusive warp scan
#pragma unroll
    for (int d = 1; d < 32; d <<= 1) {
        const int t = __shfl_up_sync(0xffffffffu, s, d);
        if (lane >= d) s += t;
    }
    const int total = __shfl_sync(0xffffffffu, s, 31);
    int base = 0;
    if (lane == 31) base = atomicAdd(&g_cursor, total);
    base = __shfl_sync(0xffffffffu, base, 31);
    const int off = base + s - c;  // exclusive within warp
    if (v < nN) { g_off[v] = off; g_cur[v] = off; }
}

__global__ __launch_bounds__(256) void scatter_kernel(const void* __restrict__ ei_raw,
                                                      int nE, int nN) {
    const int e = blockIdx.x * blockDim.x + threadIdx.x;
    const int is64 = g_is64;
    if (e < nE) {
        const int dst = load_idx(ei_raw, is64, e);
        const int src = load_idx(ei_raw, is64, (size_t)nE + e);
        if ((unsigned)dst < (unsigned)nN && (unsigned)src < (unsigned)nN) {
            const int pos = atomicAdd(&g_cur[dst], 1);
            g_pairs[pos] = make_int2(e, src);
        }
    }
}

// ---------------------------------------------------------------------------
// pre = x @ W1[0:128,:] + b1        (N x 128, K=128)
// ---------------------------------------------------------------------------
__global__ __launch_bounds__(256) void pre_kernel(const float* __restrict__ x,
                                                  const float* __restrict__ W1,
                                                  const float* __restrict__ b1,
                                                  int n) {
    __shared__ float As[64][33];
    __shared__ float Ws[32][128];
    const int tid = threadIdx.x;
    const int n0 = blockIdx.x * 64;
    const int rg = tid & 15;
    const int cg = tid >> 4;

    float acc[4][8];
#pragma unroll
    for (int i = 0; i < 4; i++)
#pragma unroll
        for (int j = 0; j < 8; j++) acc[i][j] = 0.f;

    for (int k0 = 0; k0 < 128; k0 += 32) {
        {
            const int r = tid >> 3;
            const int kq = (tid & 7) * 4;
#pragma unroll
            for (int rr = 0; rr < 64; rr += 32) {
                const int row = r + rr;
                const int node = n0 + row;
                float4 v = make_float4(0.f, 0.f, 0.f, 0.f);
                if (node < n) v = *(const float4*)&x[(size_t)node * 128 + k0 + kq];
                As[row][kq] = v.x; As[row][kq + 1] = v.y;
                As[row][kq + 2] = v.z; As[row][kq + 3] = v.w;
            }
        }
        {
            const int k = tid >> 5;
            const int c = (tid & 31) * 4;
#pragma unroll
            for (int kk = 0; kk < 32; kk += 8)
                *(float4*)&Ws[k + kk][c] =
                    *(const float4*)&W1[(size_t)(k0 + k + kk) * 128 + c];
        }
        __syncthreads();
#pragma unroll
        for (int k2 = 0; k2 < 32; k2++) {
            const float4 w0 = *(const float4*)&Ws[k2][cg * 8];
            const float4 w1 = *(const float4*)&Ws[k2][cg * 8 + 4];
#pragma unroll
            for (int i = 0; i < 4; i++) {
                const float a = As[rg * 4 + i][k2];
                acc[i][0] += a * w0.x; acc[i][1] += a * w0.y;
                acc[i][2] += a * w0.z; acc[i][3] += a * w0.w;
                acc[i][4] += a * w1.x; acc[i][5] += a * w1.y;
                acc[i][6] += a * w1.z; acc[i][7] += a * w1.w;
            }
        }
        __syncthreads();
    }

    const float4 bb0 = *(const float4*)&b1[cg * 8];
    const float4 bb1 = *(const float4*)&b1[cg * 8 + 4];
#pragma unroll
    for (int i = 0; i < 4; i++) {
        const int node = n0 + rg * 4 + i;
        if (node < n) {
            float4 o0 = make_float4(acc[i][0] + bb0.x, acc[i][1] + bb0.y,
                                    acc[i][2] + bb0.z, acc[i][3] + bb0.w);
            float4 o1 = make_float4(acc[i][4] + bb1.x, acc[i][5] + bb1.y,
                                    acc[i][6] + bb1.z, acc[i][7] + bb1.w);
            *(float4*)&g_pre[(size_t)node * 128 + cg * 8] = o0;
            *(float4*)&g_pre[(size_t)node * 128 + cg * 8 + 4] = o1;
        }
    }
}

// ---------------------------------------------------------------------------
// Aggregate v2: one warp per node, chunk-of-4 software pipeline.
//   M[v] = mean_e relu(pre[src_e] + ea[e] @ W1[128:144,:])
// Chunk load: 4 pairs coalesced (lanes 0-3), broadcast by shfl, then 4 pre
// gathers + 4 ea loads issued back-to-back (MLP ~8/lane). Two-stage pipeline:
// chunk i+1 loads in flight while chunk i computes.
// ---------------------------------------------------------------------------
struct Chunk {
    float4 pr[4];
    float  eav[4];
    int    m;
};

__device__ __forceinline__ void load_chunk(Chunk& c, int i, int end, int lane,
                                           const float4* __restrict__ pre4,
                                           const float* __restrict__ ea) {
    c.m = end - i;
    if (c.m > 4) c.m = 4;
    int2 p = make_int2(0, 0);
    if (lane < c.m) p = g_pairs[i + lane];
#pragma unroll
    for (int j = 0; j < 4; j++) {
        const int ej = __shfl_sync(0xffffffffu, p.x, j);
        const int sj = __shfl_sync(0xffffffffu, p.y, j);
        if (j < c.m) {
            c.pr[j]  = pre4[(size_t)sj * 32 + lane];
            c.eav[j] = (lane < 16) ? ea[(size_t)ej * 16 + lane] : 0.f;
        }
    }
}

__device__ __forceinline__ void compute_chunk(const Chunk& c, float4& acc,
                                              const float4 (*W1b)[32], int lane) {
#pragma unroll
    for (int j = 0; j < 4; j++) {
        if (j >= c.m) break;
        float4 t = make_float4(0.f, 0.f, 0.f, 0.f);
#pragma unroll
        for (int k = 0; k < 16; k++) {
            const float a = __shfl_sync(0xffffffffu, c.eav[j], k);
            const float4 w = W1b[k][lane];
            t.x += a * w.x; t.y += a * w.y; t.z += a * w.z; t.w += a * w.w;
        }
        acc.x += fmaxf(c.pr[j].x + t.x, 0.f);
        acc.y += fmaxf(c.pr[j].y + t.y, 0.f);
        acc.z += fmaxf(c.pr[j].z + t.z, 0.f);
        acc.w += fmaxf(c.pr[j].w + t.w, 0.f);
    }
}

__global__ __launch_bounds__(256) void agg_kernel(const float* __restrict__ ea,
                                                  const float* __restrict__ W1,
                                                  int nN) {
    __shared__ float4 W1b[16][32];
    const int tid = threadIdx.x;
    for (int idx = tid; idx < 512; idx += 256) {
        const int k = idx >> 5, c = idx & 31;
        W1b[k][c] = *(const float4*)&W1[(size_t)(128 + k) * 128 + c * 4];
    }
    __syncthreads();

    const int lane = tid & 31;
    const int v = blockIdx.x * 8 + (tid >> 5);
    if (v >= nN) return;

    const int beg = g_off[v];
    const int cnt = g_cnt[v];
    const int end = beg + cnt;
    const float4* pre4 = (const float4*)g_pre;

    float4 acc = make_float4(0.f, 0.f, 0.f, 0.f);

    Chunk c0, c1;
    int i = beg;
    if (i < end) {
        load_chunk(c0, i, end, lane, pre4, ea);
        i += 4;
        while (i < end) {
            load_chunk(c1, i, end, lane, pre4, ea);   // prefetch next
            i += 4;
            compute_chunk(c0, acc, W1b, lane);        // compute current
            c0 = c1;
        }
        compute_chunk(c0, acc, W1b, lane);
    }

    const float inv = (cnt > 0) ? (1.f / (float)cnt) : 0.f;
    acc.x *= inv; acc.y *= inv; acc.z *= inv; acc.w *= inv;
    ((float4*)g_M)[(size_t)v * 32 + lane] = acc;
}

// ---------------------------------------------------------------------------
// Node kernel: fused 3-GEMM chain on 64-node tiles.
//   h1 = cnt>0 ? M @ W2 + b2 : 0
//   h2 = relu(h1 @ W3 + b3)
//   out = h2 @ W4 + b4
// ---------------------------------------------------------------------------
__device__ __forceinline__ void gemm128(const float* __restrict__ Ain,
                                        const float* __restrict__ Wg,
                                        float* __restrict__ Wc,
                                        float acc[4][8], int rg, int cg, int tid) {
#pragma unroll
    for (int i = 0; i < 4; i++)
#pragma unroll
        for (int j = 0; j < 8; j++) acc[i][j] = 0.f;

    for (int k0 = 0; k0 < 128; k0 += 32) {
        const int k = tid >> 5;
        const int c = (tid & 31) * 4;
#pragma unroll
        for (int kk = 0; kk < 32; kk += 8)
            *(float4*)&Wc[(k + kk) * 128 + c] =
                *(const float4*)&Wg[(size_t)(k0 + k + kk) * 128 + c];
        __syncthreads();
#pragma unroll
        for (int k2 = 0; k2 < 32; k2++) {
            const float4 w0 = *(const float4*)&Wc[k2 * 128 + cg * 8];
            const float4 w1 = *(const float4*)&Wc[k2 * 128 + cg * 8 + 4];
#pragma unroll
            for (int i = 0; i < 4; i++) {
                const float a = Ain[(rg * 4 + i) * 129 + k0 + k2];
                acc[i][0] += a * w0.x; acc[i][1] += a * w0.y;
                acc[i][2] += a * w0.z; acc[i][3] += a * w0.w;
                acc[i][4] += a * w1.x; acc[i][5] += a * w1.y;
                acc[i][6] += a * w1.z; acc[i][7] += a * w1.w;
            }
        }
        __syncthreads();
    }
}

__global__ __launch_bounds__(256) void node_kernel(const float* __restrict__ W2,
                                                   const float* __restrict__ b2,
                                                   const float* __restrict__ W3,
                                                   const float* __restrict__ b3,
                                                   const float* __restrict__ W4,
                                                   const float* __restrict__ b4,
                                                   float* __restrict__ out, int n) {
    extern __shared__ float sm[];
    float* A  = sm;                      // [64][129]
    float* B  = sm + 64 * 129;           // [64][129]
    float* Wc = sm + 2 * 64 * 129;       // [32][128]
    float* zf = Wc + 32 * 128;           // [64] cnt==0 flags

    const int tid = threadIdx.x;
    const int n0 = blockIdx.x * 64;
    const int rg = tid & 15;
    const int cg = tid >> 4;

    // Load mean operand (already divided) into A, flag empty nodes.
    {
        const int r = tid >> 2;
        const int q = (tid & 3) * 4;
        const int node = n0 + r;
        if ((tid & 3) == 0)
            zf[r] = (node < n && g_cnt[node] > 0) ? 0.f : 1.f;
#pragma unroll
        for (int k = q; k < 128; k += 16) {
            float4 v = make_float4(0.f, 0.f, 0.f, 0.f);
            if (node < n) v = *(const float4*)&g_M[(size_t)node * 128 + k];
            A[r * 129 + k]     = v.x;
            A[r * 129 + k + 1] = v.y;
            A[r * 129 + k + 2] = v.z;
            A[r * 129 + k + 3] = v.w;
        }
    }
    __syncthreads();

    float acc[4][8];

    // Stage 1: B = (cnt>0) ? A@W2 + b2 : 0
    gemm128(A, W2, Wc, acc, rg, cg, tid);
    {
        const float4 bb0 = *(const float4*)&b2[cg * 8];
        const float4 bb1 = *(const float4*)&b2[cg * 8 + 4];
        const float bb[8] = {bb0.x, bb0.y, bb0.z, bb0.w, bb1.x, bb1.y, bb1.z, bb1.w};
#pragma unroll
        for (int i = 0; i < 4; i++) {
            const int row = rg * 4 + i;
            const float zero = zf[row];
#pragma unroll
            for (int j = 0; j < 8; j++)
                B[row * 129 + cg * 8 + j] = (zero > 0.f) ? 0.f : (acc[i][j] + bb[j]);
        }
    }
    __syncthreads();

    // Stage 2: A = relu(B@W3 + b3)
    gemm128(B, W3, Wc, acc, rg, cg, tid);
    {
        const float4 bb0 = *(const float4*)&b3[cg * 8];
        const float4 bb1 = *(const float4*)&b3[cg * 8 + 4];
        const float bb[8] = {bb0.x, bb0.y, bb0.z, bb0.w, bb1.x, bb1.y, bb1.z, bb1.w};
#pragma unroll
        for (int i = 0; i < 4; i++) {
            const int row = rg * 4 + i;
#pragma unroll
            for (int j = 0; j < 8; j++)
                A[row * 129 + cg * 8 + j] = fmaxf(acc[i][j] + bb[j], 0.f);
        }
    }
    __syncthreads();

    // Stage 3: out = A@W4 + b4
    gemm128(A, W4, Wc, acc, rg, cg, tid);
    {
        const float4 bb0 = *(const float4*)&b4[cg * 8];
        const float4 bb1 = *(const float4*)&b4[cg * 8 + 4];
#pragma unroll
        for (int i = 0; i < 4; i++) {
            const int node = n0 + rg * 4 + i;
            if (node < n) {
                float4 o0 = make_float4(acc[i][0] + bb0.x, acc[i][1] + bb0.y,
                                        acc[i][2] + bb0.z, acc[i][3] + bb0.w);
                float4 o1 = make_float4(acc[i][4] + bb1.x, acc[i][5] + bb1.y,
                                        acc[i][6] + bb1.z, acc[i][7] + bb1.w);
                *(float4*)&out[(size_t)node * 128 + cg * 8] = o0;
                *(float4*)&out[(size_t)node * 128 + cg * 8 + 4] = o1;
            }
        }
    }
}

// ---------------------------------------------------------------------------
extern "C" void kernel_launch(void* const* d_in, const int* in_sizes, int n_in,
                              void* d_out, int out_size) {
    const float* x  = (const float*)d_in[0];
    const void*  ei = d_in[1];          // int32 or int64 — detected on device
    const float* ea = (const float*)d_in[2];
    // d_in[3] = batch (unused)
    const float* W1 = (const float*)d_in[4];
    const float* b1 = (const float*)d_in[5];
    const float* W2 = (const float*)d_in[6];
    const float* b2 = (const float*)d_in[7];
    const float* W3 = (const float*)d_in[8];
    const float* b3 = (const float*)d_in[9];
    const float* W4 = (const float*)d_in[10];
    const float* b4 = (const float*)d_in[11];
    float* out = (float*)d_out;

    const int n  = in_sizes[0] / 128;   // nodes
    const int nE = in_sizes[1] / 2;     // edges

    void* pC = nullptr; void* pX = nullptr;
    cudaGetSymbolAddress(&pC, g_cnt);
    cudaGetSymbolAddress(&pX, g_cursor);
    cudaMemsetAsync(pC, 0, (size_t)n * sizeof(int), 0);
    cudaMemsetAsync(pX, 0, sizeof(int), 0);

    const int ebl = (nE + 255) / 256;
    const int nbl = (n + 255) / 256;

    detect_kernel<<<1, 256>>>((const int*)ei, 2 * nE);
    hist_kernel<<<ebl, 256>>>(ei, nE, n);
    offset_kernel<<<nbl, 256>>>(n);
    scatter_kernel<<<ebl, 256>>>(ei, nE, n);

    const int nb64 = (n + 63) / 64;
    pre_kernel<<<nb64, 256>>>(x, W1, b1, n);
    agg_kernel<<<(n + 7) / 8, 256>>>(ea, W1, n);

    const size_t shmem = (size_t)(2 * 64 * 129 + 32 * 128 + 64) * sizeof(float);
    cudaFuncSetAttribute(node_kernel,
                         cudaFuncAttributeMaxDynamicSharedMemorySize, (int)shmem);
    node_kernel<<<nb64, 256, shmem>>>(W2, b2, W3, b3, W4, b4, out, n);
}